// round 16
// baseline (speedup 1.0000x reference)
#include <cuda_runtime.h>
#include <cuda_fp16.h>
#include <cstdint>

// ============================================================================
// dims
// ============================================================================
#define B_DIM 32
#define F_DIM 1024
#define L_DIM 1000
#define N_DIM 2048
#define LPAD  1024

// GEMM tiling (per batch: M=N_DIM rows n, N=L cols l, K=F)
#define TM 128
#define TN 128
#define KC 32                    // K halves per stage (64B rows)
#define STAGES 3
#define KITERS (F_DIM / KC)      // 32

// SMEM: padded row stride 40 halves = 80B -> ldmatrix conflict-free
#define RSTRIDE_B 80
#define A_STAGE_BYTES (TM * RSTRIDE_B)                     // 10240
#define B_STAGE_BYTES (TN * RSTRIDE_B)                     // 10240
#define STAGE_BYTES (A_STAGE_BYTES + B_STAGE_BYTES)        // 20480
#define SMEM_BYTES (STAGES * STAGE_BYTES)                  // 61440 (3 CTAs/SM)

// ============================================================================
// device scratch (static globals: allocation-guard safe)
// ============================================================================
__device__ __align__(1024) __half g_A [(size_t)N_DIM * F_DIM];        // 4 MB
__device__ __align__(1024) __half g_Xt[(size_t)B_DIM * LPAD * F_DIM]; // 67 MB

// ============================================================================
// helpers
// ============================================================================
__device__ __forceinline__ uint32_t smem_u32(const void* p) {
    uint32_t a;
    asm("{ .reg .u64 t; cvta.to.shared.u64 t, %1; cvt.u32.u64 %0, t; }"
        : "=r"(a) : "l"(p));
    return a;
}

#define CP_ASYNC16(dst, src) \
    asm volatile("cp.async.cg.shared.global [%0], [%1], 16;" \
                 :: "r"(dst), "l"(src) : "memory")
#define CP_COMMIT() asm volatile("cp.async.commit_group;" ::: "memory")
#define CP_WAIT(n)  asm volatile("cp.async.wait_group %0;" :: "n"(n) : "memory")

#define LDSM_X4(r0, r1, r2, r3, addr) \
    asm volatile("ldmatrix.sync.aligned.m8n8.x4.shared.b16 {%0,%1,%2,%3}, [%4];" \
                 : "=r"(r0), "=r"(r1), "=r"(r2), "=r"(r3) : "r"(addr))

__device__ __forceinline__ void mma_f16(float d[4],
                                        uint32_t a0, uint32_t a1,
                                        uint32_t a2, uint32_t a3,
                                        uint32_t b0, uint32_t b1) {
    asm volatile(
        "mma.sync.aligned.m16n8k16.row.col.f32.f16.f16.f32 "
        "{%0, %1, %2, %3}, {%4, %5, %6, %7}, {%8, %9}, {%0, %1, %2, %3};"
        : "+f"(d[0]), "+f"(d[1]), "+f"(d[2]), "+f"(d[3])
        : "r"(a0), "r"(a1), "r"(a2), "r"(a3), "r"(b0), "r"(b1));
}

// ============================================================================
// merged prep (one launch): z < PZ_X -> Xt tiles; z >= PZ_X -> A tiles
// ============================================================================
#define PZ_X (B_DIM)                       // 32 z-slices for X
#define PZ_A (PZ_X + 2)                    // +2 z-slices for A

__global__ void prep_kernel(const float* __restrict__ X,
                            const float* __restrict__ C,
                            const float* __restrict__ W) {
    const int tx = threadIdx.x, ty = threadIdx.y;
    if (blockIdx.z < PZ_X) {
        __shared__ float tile[64][33];
        const int l0 = blockIdx.x * 32;
        const int f0 = blockIdx.y * 64;
        const int b  = blockIdx.z;
        const int tid = ty * 32 + tx;
        const float* Xb = X + (size_t)b * F_DIM * L_DIM;
        const int l = l0 + tx;
#pragma unroll
        for (int i = 0; i < 64; i += 8)
            tile[ty + i][tx] = (l < L_DIM)
                ? Xb[(size_t)(f0 + ty + i) * L_DIM + l] : 0.0f;
        __syncthreads();
        const int row = tid >> 3;
        const int c8  = tid & 7;
        __half2 h[4];
#pragma unroll
        for (int m = 0; m < 4; m++)
            h[m] = __floats2half2_rn(tile[8 * c8 + 2 * m][row],
                                     tile[8 * c8 + 2 * m + 1][row]);
        __half* Xtb = g_Xt + (size_t)b * LPAD * F_DIM;
        *reinterpret_cast<int4*>(Xtb + (size_t)(l0 + row) * F_DIM + f0 + 8 * c8) =
            *reinterpret_cast<int4*>(h);
    } else {
        __shared__ float tile[32][33];
        const int zi = blockIdx.z - PZ_X;          // 0..1
        const int n0 = (blockIdx.x + zi * 32) * 32;
        const int f0 = blockIdx.y * 64;
        const float w = W[n0 + tx];
#pragma unroll
        for (int half = 0; half < 2; half++) {
            const int fh = f0 + half * 32;
#pragma unroll
            for (int i = 0; i < 32; i += 8)
                tile[ty + i][tx] = C[(size_t)(fh + ty + i) * N_DIM + n0 + tx] * w;
            __syncthreads();
            if (tx < 16) {
#pragma unroll
                for (int i = 0; i < 32; i += 8) {
                    const int n = n0 + ty + i;
                    __half2 v = __floats2half2_rn(tile[2 * tx][ty + i],
                                                  tile[2 * tx + 1][ty + i]);
                    *reinterpret_cast<__half2*>(
                        g_A + (size_t)n * F_DIM + fh + 2 * tx) = v;
                }
            }
            __syncthreads();
        }
    }
}

// ============================================================================
// GEMM: out[b, n0:+128, l0:+128] = A x Xt^T
//   256 threads = 8 warps: 2(m) x 4(n), warp tile 64 x 32 (64 accum regs),
//   3-stage cp.async, 3 CTAs/SM = 24 warps/SM (occupancy experiment)
// ============================================================================
__global__ void __launch_bounds__(256, 3)
gemm_kernel(float* __restrict__ out) {
    extern __shared__ __align__(128) char smem[];
    const uint32_t sbase = smem_u32(smem);

    const int tid = threadIdx.x;
    const int wid = tid >> 5;
    const int lid = tid & 31;
    const int g = lid >> 2;
    const int t = lid & 3;

    const int wm = wid & 1;          // 0..1 -> 64 m-rows each
    const int wn = wid >> 1;         // 0..3 -> 32 n-cols each

    const int n0 = blockIdx.x * TM;
    const int l0 = blockIdx.y * TN;
    const int b  = blockIdx.z;

    const __half* Abase = g_A  + (size_t)n0 * F_DIM;
    const __half* Bbase = g_Xt + ((size_t)b * LPAD + l0) * F_DIM;

    float d[4][4][4];
#pragma unroll
    for (int mi = 0; mi < 4; mi++)
#pragma unroll
        for (int ni = 0; ni < 4; ni++)
#pragma unroll
            for (int r = 0; r < 4; r++) d[mi][ni][r] = 0.0f;

    const int c_row = tid >> 2;      // 0..63, +64 per i
    const int c_cb  = tid & 3;

    auto load_stage = [&](int s, int k) {
        const int k0 = k * KC;
        const uint32_t sa = sbase + s * STAGE_BYTES;
        const uint32_t sb = sa + A_STAGE_BYTES;
#pragma unroll
        for (int i = 0; i < 2; i++) {
            int row = c_row + i * 64;
            CP_ASYNC16(sa + row * RSTRIDE_B + c_cb * 16,
                       Abase + (size_t)row * F_DIM + k0 + c_cb * 8);
        }
#pragma unroll
        for (int i = 0; i < 2; i++) {
            int row = c_row + i * 64;
            CP_ASYNC16(sb + row * RSTRIDE_B + c_cb * 16,
                       Bbase + (size_t)row * F_DIM + k0 + c_cb * 8);
        }
        CP_COMMIT();
    };

    // prologue: stages 0,1 (prefetch distance 2)
    load_stage(0, 0);
    load_stage(1, 1);

    const int lrow = lid & 15;
    const int lchunk = (lid >> 4) * 16;

    for (int k = 0; k < KITERS; k++) {
        CP_WAIT(1);                  // stage k resident
        __syncthreads();             // all warps done with stage (k-1)%3
        if (k + 2 < KITERS) load_stage((k + 2) % STAGES, k + 2);

        const uint32_t sa = sbase + (k % STAGES) * STAGE_BYTES;
        const uint32_t sb = sa + A_STAGE_BYTES;

#pragma unroll
        for (int kk = 0; kk < 2; kk++) {
            const uint32_t koff = kk * 32 + lchunk;
            uint32_t af[4][4];
#pragma unroll
            for (int mi = 0; mi < 4; mi++) {
                uint32_t addr = sa + (wm * 64 + mi * 16 + lrow) * RSTRIDE_B + koff;
                LDSM_X4(af[mi][0], af[mi][1], af[mi][2], af[mi][3], addr);
            }
            uint32_t bf[4][2];
#pragma unroll
            for (int p = 0; p < 2; p++) {
                uint32_t addr = sb + (wn * 32 + p * 16 + lrow) * RSTRIDE_B + koff;
                uint32_t m0, m1, m2, m3;
                LDSM_X4(m0, m1, m2, m3, addr);
                bf[2 * p][0] = m0; bf[2 * p][1] = m2;
                bf[2 * p + 1][0] = m1; bf[2 * p + 1][1] = m3;
            }
#pragma unroll
            for (int mi = 0; mi < 4; mi++)
#pragma unroll
                for (int ni = 0; ni < 4; ni++)
                    mma_f16(d[mi][ni], af[mi][0], af[mi][1], af[mi][2], af[mi][3],
                            bf[ni][0], bf[ni][1]);
        }
    }

    // ---- epilogue: direct global float2 stores ----
#pragma unroll
    for (int mi = 0; mi < 4; mi++) {
        const int row = n0 + wm * 64 + mi * 16 + g;
        float* r0 = out + ((size_t)b * N_DIM + row) * L_DIM;
        float* r1 = r0 + 8 * L_DIM;
#pragma unroll
        for (int ni = 0; ni < 4; ni++) {
            const int l = l0 + wn * 32 + ni * 8 + 2 * t;
            if (l < L_DIM) {
                *reinterpret_cast<float2*>(r0 + l) =
                    make_float2(d[mi][ni][0], d[mi][ni][1]);
                *reinterpret_cast<float2*>(r1 + l) =
                    make_float2(d[mi][ni][2], d[mi][ni][3]);
            }
        }
    }
}

// ============================================================================
// host
// ============================================================================
extern "C" void kernel_launch(void* const* d_in, const int* in_sizes, int n_in,
                              void* d_out, int out_size) {
    const float* X = (const float*)d_in[0];
    const float* C = (const float*)d_in[1];
    const float* W = (const float*)d_in[2];
    for (int i = 0; i < n_in; i++) {
        if (in_sizes[i] == B_DIM * F_DIM * L_DIM) X = (const float*)d_in[i];
        else if (in_sizes[i] == F_DIM * N_DIM)    C = (const float*)d_in[i];
        else if (in_sizes[i] == N_DIM)            W = (const float*)d_in[i];
    }

    cudaFuncSetAttribute(gemm_kernel,
                         cudaFuncAttributeMaxDynamicSharedMemorySize, SMEM_BYTES);

    prep_kernel<<<dim3(LPAD / 32, F_DIM / 64, PZ_A), dim3(32, 8)>>>(X, C, W);
    gemm_kernel<<<dim3(N_DIM / TM, LPAD / TN, B_DIM), 256, SMEM_BYTES>>>(
        (float*)d_out);
}

// round 17
// speedup vs baseline: 1.0707x; 1.0707x over previous
#include <cuda_runtime.h>
#include <cuda_fp16.h>
#include <cstdint>

// ============================================================================
// dims
// ============================================================================
#define B_DIM 32
#define F_DIM 1024
#define L_DIM 1000
#define N_DIM 2048
#define LPAD  1024

// GEMM tiling (per batch: M=N_DIM rows n, N=L cols l, K=F)
#define TM 128
#define TN 128
#define KC 32                    // K halves per chunk
#define STAGES 4                 // A-only smem stages
#define KITERS (F_DIM / KC)      // 32

// SMEM: A only; padded row stride 40 halves = 80B -> ldmatrix conflict-free
#define RSTRIDE_A 80
#define A_STAGE_BYTES (TM * RSTRIDE_A)                     // 10240
#define SMEM_BYTES (STAGES * A_STAGE_BYTES)                // 40960 (2 CTAs/SM)

// ============================================================================
// device scratch (static globals: allocation-guard safe)
// ============================================================================
__device__ __align__(1024) __half g_A [(size_t)N_DIM * F_DIM];        // 4 MB
__device__ __align__(1024) __half g_Xt[(size_t)B_DIM * LPAD * F_DIM]; // 67 MB

// ============================================================================
// helpers
// ============================================================================
__device__ __forceinline__ uint32_t smem_u32(const void* p) {
    uint32_t a;
    asm("{ .reg .u64 t; cvta.to.shared.u64 t, %1; cvt.u32.u64 %0, t; }"
        : "=r"(a) : "l"(p));
    return a;
}

#define CP_ASYNC16(dst, src) \
    asm volatile("cp.async.cg.shared.global [%0], [%1], 16;" \
                 :: "r"(dst), "l"(src) : "memory")
#define CP_COMMIT() asm volatile("cp.async.commit_group;" ::: "memory")
#define CP_WAIT(n)  asm volatile("cp.async.wait_group %0;" :: "n"(n) : "memory")

#define LDSM_X4(r0, r1, r2, r3, addr) \
    asm volatile("ldmatrix.sync.aligned.m8n8.x4.shared.b16 {%0,%1,%2,%3}, [%4];" \
                 : "=r"(r0), "=r"(r1), "=r"(r2), "=r"(r3) : "r"(addr))

__device__ __forceinline__ void mma_f16(float d[4],
                                        uint32_t a0, uint32_t a1,
                                        uint32_t a2, uint32_t a3,
                                        uint32_t b0, uint32_t b1) {
    asm volatile(
        "mma.sync.aligned.m16n8k16.row.col.f32.f16.f16.f32 "
        "{%0, %1, %2, %3}, {%4, %5, %6, %7}, {%8, %9}, {%0, %1, %2, %3};"
        : "+f"(d[0]), "+f"(d[1]), "+f"(d[2]), "+f"(d[3])
        : "r"(a0), "r"(a1), "r"(a2), "r"(a3), "r"(b0), "r"(b1));
}

// ============================================================================
// merged prep (one launch): z < PZ_X -> Xt tiles; z >= PZ_X -> A tiles
// ============================================================================
#define PZ_X (B_DIM)
#define PZ_A (PZ_X + 2)

__global__ void prep_kernel(const float* __restrict__ X,
                            const float* __restrict__ C,
                            const float* __restrict__ W) {
    const int tx = threadIdx.x, ty = threadIdx.y;
    if (blockIdx.z < PZ_X) {
        __shared__ float tile[64][33];
        const int l0 = blockIdx.x * 32;
        const int f0 = blockIdx.y * 64;
        const int b  = blockIdx.z;
        const int tid = ty * 32 + tx;
        const float* Xb = X + (size_t)b * F_DIM * L_DIM;
        const int l = l0 + tx;
#pragma unroll
        for (int i = 0; i < 64; i += 8)
            tile[ty + i][tx] = (l < L_DIM)
                ? Xb[(size_t)(f0 + ty + i) * L_DIM + l] : 0.0f;
        __syncthreads();
        const int row = tid >> 3;
        const int c8  = tid & 7;
        __half2 h[4];
#pragma unroll
        for (int m = 0; m < 4; m++)
            h[m] = __floats2half2_rn(tile[8 * c8 + 2 * m][row],
                                     tile[8 * c8 + 2 * m + 1][row]);
        __half* Xtb = g_Xt + (size_t)b * LPAD * F_DIM;
        *reinterpret_cast<int4*>(Xtb + (size_t)(l0 + row) * F_DIM + f0 + 8 * c8) =
            *reinterpret_cast<int4*>(h);
    } else {
        __shared__ float tile[32][33];
        const int zi = blockIdx.z - PZ_X;
        const int n0 = (blockIdx.x + zi * 32) * 32;
        const int f0 = blockIdx.y * 64;
        const float w = W[n0 + tx];
#pragma unroll
        for (int half = 0; half < 2; half++) {
            const int fh = f0 + half * 32;
#pragma unroll
            for (int i = 0; i < 32; i += 8)
                tile[ty + i][tx] = C[(size_t)(fh + ty + i) * N_DIM + n0 + tx] * w;
            __syncthreads();
            if (tx < 16) {
#pragma unroll
                for (int i = 0; i < 32; i += 8) {
                    const int n = n0 + ty + i;
                    __half2 v = __floats2half2_rn(tile[2 * tx][ty + i],
                                                  tile[2 * tx + 1][ty + i]);
                    *reinterpret_cast<__half2*>(
                        g_A + (size_t)n * F_DIM + fh + 2 * tx) = v;
                }
            }
            __syncthreads();
        }
    }
}

// ============================================================================
// GEMM: out[b, n0:+128, l0:+128] = A x Xt^T
//   256 threads = 8 warps: 2(m) x 4(n), warp tile 64 x 32
//   A: 4-stage cp.async smem + ldmatrix (barrier-protected)
//   B: direct per-thread LDG from Xt (L2), pipelined one k16-step in regs —
//      no smem, no barrier on the B path. 2 CTAs/SM = 16 warps/SM.
// ============================================================================
__global__ void __launch_bounds__(256, 2)
gemm_kernel(float* __restrict__ out) {
    extern __shared__ __align__(128) char smem[];
    const uint32_t sbase = smem_u32(smem);

    const int tid = threadIdx.x;
    const int wid = tid >> 5;
    const int lid = tid & 31;
    const int g = lid >> 2;
    const int t = lid & 3;

    const int wm = wid & 1;          // 0..1 -> 64 m-rows each
    const int wn = wid >> 1;         // 0..3 -> 32 n(l)-cols each

    const int n0 = blockIdx.x * TM;
    const int l0 = blockIdx.y * TN;
    const int b  = blockIdx.z;

    const __half* Abase = g_A + (size_t)n0 * F_DIM;
    // per-thread B base: row l = l0 + wn*32 + g, col offset 2t halves
    const __half* Bptr = g_Xt + ((size_t)b * LPAD + l0 + wn * 32 + g) * F_DIM
                         + 2 * t;

    float d[4][4][4];
#pragma unroll
    for (int mi = 0; mi < 4; mi++)
#pragma unroll
        for (int ni = 0; ni < 4; ni++)
#pragma unroll
            for (int r = 0; r < 4; r++) d[mi][ni][r] = 0.0f;

    // A cp.async mapping: 128 rows x 4 chunks of 16B over 256 threads
    const int c_row = tid >> 2;      // 0..63, +64
    const int c_cb  = tid & 3;
    auto load_A = [&](int k) {
        const int k0 = k * KC;
        const uint32_t sa = sbase + (k % STAGES) * A_STAGE_BYTES;
#pragma unroll
        for (int i = 0; i < 2; i++) {
            int row = c_row + i * 64;
            CP_ASYNC16(sa + row * RSTRIDE_A + c_cb * 16,
                       Abase + (size_t)row * F_DIM + k0 + c_cb * 8);
        }
    };

    // B fragment loader for global k16-step s (s = 2k + kk)
    auto load_b = [&](int s, uint32_t bf[4][2]) {
#pragma unroll
        for (int ni = 0; ni < 4; ni++) {
            const __half* p = Bptr + (size_t)ni * 8 * F_DIM + s * 16;
            bf[ni][0] = *reinterpret_cast<const uint32_t*>(p);
            bf[ni][1] = *reinterpret_cast<const uint32_t*>(p + 8);
        }
    };

    // ---- prologue ----
    load_A(0); CP_COMMIT();
    load_A(1); CP_COMMIT();
    load_A(2); CP_COMMIT();
    uint32_t bc[4][2], bn[4][2];
    load_b(0, bc);

    const int lrow = lid & 15;
    const int lchunk = (lid >> 4) * 16;

    // invariant: commits at iter-k top = 3+k; CP_WAIT(2) => chunks <= k resident
    for (int k = 0; k < KITERS; k++) {
        CP_WAIT(2);
        __syncthreads();             // all warps done with stage (k-1)%4

        load_b(2 * k + 1, bn);       // B for kk=1 (no smem dependency)
        if (k + 3 < KITERS) load_A(k + 3);
        CP_COMMIT();                 // unconditional: keeps commit count exact

        const uint32_t sa = sbase + (k % STAGES) * A_STAGE_BYTES;

        // ---- kk = 0 ----
        {
            uint32_t af[4][4];
#pragma unroll
            for (int mi = 0; mi < 4; mi++) {
                uint32_t addr = sa + (wm * 64 + mi * 16 + lrow) * RSTRIDE_A
                                + lchunk;
                LDSM_X4(af[mi][0], af[mi][1], af[mi][2], af[mi][3], addr);
            }
#pragma unroll
            for (int mi = 0; mi < 4; mi++)
#pragma unroll
                for (int ni = 0; ni < 4; ni++)
                    mma_f16(d[mi][ni], af[mi][0], af[mi][1], af[mi][2], af[mi][3],
                            bc[ni][0], bc[ni][1]);
        }
        if (k + 1 < KITERS) load_b(2 * k + 2, bc);   // next chunk kk=0
        // ---- kk = 1 ----
        {
            uint32_t af[4][4];
#pragma unroll
            for (int mi = 0; mi < 4; mi++) {
                uint32_t addr = sa + (wm * 64 + mi * 16 + lrow) * RSTRIDE_A
                                + 32 + lchunk;
                LDSM_X4(af[mi][0], af[mi][1], af[mi][2], af[mi][3], addr);
            }
#pragma unroll
            for (int mi = 0; mi < 4; mi++)
#pragma unroll
                for (int ni = 0; ni < 4; ni++)
                    mma_f16(d[mi][ni], af[mi][0], af[mi][1], af[mi][2], af[mi][3],
                            bn[ni][0], bn[ni][1]);
        }
    }

    // ---- epilogue: direct global float2 stores ----
#pragma unroll
    for (int mi = 0; mi < 4; mi++) {
        const int row = n0 + wm * 64 + mi * 16 + g;
        float* r0 = out + ((size_t)b * N_DIM + row) * L_DIM;
        float* r1 = r0 + 8 * L_DIM;
#pragma unroll
        for (int ni = 0; ni < 4; ni++) {
            const int l = l0 + wn * 32 + ni * 8 + 2 * t;
            if (l < L_DIM) {
                *reinterpret_cast<float2*>(r0 + l) =
                    make_float2(d[mi][ni][0], d[mi][ni][1]);
                *reinterpret_cast<float2*>(r1 + l) =
                    make_float2(d[mi][ni][2], d[mi][ni][3]);
            }
        }
    }
}

// ============================================================================
// host
// ============================================================================
extern "C" void kernel_launch(void* const* d_in, const int* in_sizes, int n_in,
                              void* d_out, int out_size) {
    const float* X = (const float*)d_in[0];
    const float* C = (const float*)d_in[1];
    const float* W = (const float*)d_in[2];
    for (int i = 0; i < n_in; i++) {
        if (in_sizes[i] == B_DIM * F_DIM * L_DIM) X = (const float*)d_in[i];
        else if (in_sizes[i] == F_DIM * N_DIM)    C = (const float*)d_in[i];
        else if (in_sizes[i] == N_DIM)            W = (const float*)d_in[i];
    }

    cudaFuncSetAttribute(gemm_kernel,
                         cudaFuncAttributeMaxDynamicSharedMemorySize, SMEM_BYTES);

    prep_kernel<<<dim3(LPAD / 32, F_DIM / 64, PZ_A), dim3(32, 8)>>>(X, C, W);
    gemm_kernel<<<dim3(N_DIM / TM, LPAD / TN, B_DIM), 256, SMEM_BYTES>>>(
        (float*)d_out);
}